// round 3
// baseline (speedup 1.0000x reference)
#include <cuda_runtime.h>
#include <cuda_bf16.h>
#include <cstdint>

// Problem constants (fixed by the reference)
#define F_IN   512
#define F_OUT  256
#define MAX_NODES 100000

// Scratch for support = x @ W  (100000 x 256 fp32 = 102.4 MB). Static __device__
// array — allocation-free per harness rules.
__device__ float g_support[(size_t)MAX_NODES * F_OUT];

// ---------------------------------------------------------------------------
// Zero-init the output (it is poisoned to 0xAA by the harness).
// ---------------------------------------------------------------------------
__global__ void zero_kernel(float* __restrict__ out, int n4) {
    int i = blockIdx.x * blockDim.x + threadIdx.x;
    float4 z = {0.f, 0.f, 0.f, 0.f};
    if (i < n4) reinterpret_cast<float4*>(out)[i] = z;
}

// ---------------------------------------------------------------------------
// SGEMM: C[M,256] = A[M,512] @ B[512,256]
// 128x128 tile per block, 256 threads, 8x8 micro-tile per thread, K-step 8.
// ---------------------------------------------------------------------------
__global__ __launch_bounds__(256) void gemm_kernel(
    const float* __restrict__ A,   // [M, 512]
    const float* __restrict__ B,   // [512, 256]
    int M)
{
    __shared__ float As[8][128];   // transposed A tile: As[kk][m]
    __shared__ float Bs[8][128];   // Bs[kk][n]

    const int tid = threadIdx.x;
    const int tx  = tid & 15;      // 0..15 -> column group
    const int ty  = tid >> 4;      // 0..15 -> row group

    const int block_m = blockIdx.x * 128;
    const int block_n = blockIdx.y * 128;

    // A-tile load mapping: thread t loads A[block_m + t/2][k0 + (t&1)*4 .. +3]
    const int a_row = tid >> 1;          // 0..127
    const int a_kk  = (tid & 1) * 4;     // 0 or 4
    // B-tile load mapping: thread t loads B[k0 + t/32][block_n + (t&31)*4 ..]
    const int b_kk  = tid >> 5;          // 0..7
    const int b_col = (tid & 31) * 4;    // 0..124

    float acc[8][8];
    #pragma unroll
    for (int i = 0; i < 8; i++)
        #pragma unroll
        for (int j = 0; j < 8; j++)
            acc[i][j] = 0.f;

    const int g_arow = block_m + a_row;
    const float* a_ptr = A + (size_t)g_arow * F_IN + a_kk;
    const float* b_ptr = B + (size_t)b_kk * F_OUT + block_n + b_col;

    for (int k0 = 0; k0 < F_IN; k0 += 8) {
        // ---- load A tile (predicated on row bound) ----
        float4 av = {0.f, 0.f, 0.f, 0.f};
        if (g_arow < M) av = *reinterpret_cast<const float4*>(a_ptr + k0);
        As[a_kk + 0][a_row] = av.x;
        As[a_kk + 1][a_row] = av.y;
        As[a_kk + 2][a_row] = av.z;
        As[a_kk + 3][a_row] = av.w;
        // ---- load B tile ----
        float4 bv = *reinterpret_cast<const float4*>(b_ptr + (size_t)k0 * F_OUT);
        *reinterpret_cast<float4*>(&Bs[b_kk][b_col]) = bv;
        __syncthreads();

        #pragma unroll
        for (int kk = 0; kk < 8; kk++) {
            float4 a0 = *reinterpret_cast<const float4*>(&As[kk][ty * 8]);
            float4 a1 = *reinterpret_cast<const float4*>(&As[kk][ty * 8 + 4]);
            float4 b0 = *reinterpret_cast<const float4*>(&Bs[kk][tx * 8]);
            float4 b1 = *reinterpret_cast<const float4*>(&Bs[kk][tx * 8 + 4]);
            float af[8] = {a0.x, a0.y, a0.z, a0.w, a1.x, a1.y, a1.z, a1.w};
            float bf[8] = {b0.x, b0.y, b0.z, b0.w, b1.x, b1.y, b1.z, b1.w};
            #pragma unroll
            for (int i = 0; i < 8; i++)
                #pragma unroll
                for (int j = 0; j < 8; j++)
                    acc[i][j] = fmaf(af[i], bf[j], acc[i][j]);
        }
        __syncthreads();
    }

    // ---- store C tile ----
    #pragma unroll
    for (int i = 0; i < 8; i++) {
        int row = block_m + ty * 8 + i;
        if (row < M) {
            float* c_ptr = g_support + (size_t)row * F_OUT + block_n + tx * 8;
            float4 c0 = {acc[i][0], acc[i][1], acc[i][2], acc[i][3]};
            float4 c1 = {acc[i][4], acc[i][5], acc[i][6], acc[i][7]};
            *reinterpret_cast<float4*>(c_ptr)     = c0;
            *reinterpret_cast<float4*>(c_ptr + 4) = c1;
        }
    }
}

// ---------------------------------------------------------------------------
// SpMM: out[row] += val * support[col], edges row-sorted.
// grid.x = edge chunks of ECHUNK, grid.y = 2 feature halves of 128.
// Edges staged to SMEM (broadcast). Register accumulation within a row
// segment; atomicAdd only at segment boundaries (rows may straddle chunks).
// ---------------------------------------------------------------------------
#define ECHUNK 256
#define SPMM_UNROLL 8

__global__ __launch_bounds__(128) void spmm_kernel(
    const int*   __restrict__ erow,
    const int*   __restrict__ ecol,
    const float* __restrict__ eval,
    float*       __restrict__ out,
    int E)
{
    __shared__ int   srow[ECHUNK];
    __shared__ int   scol[ECHUNK];
    __shared__ float sval[ECHUNK];

    const int f  = blockIdx.y * 128 + threadIdx.x;   // feature index, coalesced
    const int e0 = blockIdx.x * ECHUNK;
    const int n  = min(ECHUNK, E - e0);

    for (int i = threadIdx.x; i < n; i += 128) {
        srow[i] = erow[e0 + i];
        scol[i] = ecol[e0 + i];
        sval[i] = eval[e0 + i];
    }
    // pad tail so the main loop needs no bounds checks
    for (int i = n + threadIdx.x; i < ECHUNK; i += 128) {
        scol[i] = 0;
        sval[i] = 0.f;
    }
    __syncthreads();
    if (n < ECHUNK) {
        int last = srow[n - 1];
        for (int i = n + threadIdx.x; i < ECHUNK; i += 128) srow[i] = last;
        __syncthreads();
    }

    float acc = 0.f;
    int   cur = srow[0];

    #pragma unroll 1
    for (int i = 0; i < ECHUNK; i += SPMM_UNROLL) {
        // hoist the gathers first for MLP
        float g[SPMM_UNROLL];
        #pragma unroll
        for (int j = 0; j < SPMM_UNROLL; j++) {
            g[j] = __ldg(&g_support[(size_t)scol[i + j] * F_OUT + f]);
        }
        #pragma unroll
        for (int j = 0; j < SPMM_UNROLL; j++) {
            int r = srow[i + j];
            if (r != cur) {
                atomicAdd(&out[(size_t)cur * F_OUT + f], acc);
                acc = 0.f;
                cur = r;
            }
            acc = fmaf(sval[i + j], g[j], acc);
        }
    }
    atomicAdd(&out[(size_t)cur * F_OUT + f], acc);
}

// ---------------------------------------------------------------------------
extern "C" void kernel_launch(void* const* d_in, const int* in_sizes, int n_in,
                              void* d_out, int out_size) {
    const float* x    = (const float*)d_in[0];   // [N, 512]
    const float* w    = (const float*)d_in[1];   // [512, 256]
    const int*   erow = (const int*)  d_in[2];   // [E]
    const int*   ecol = (const int*)  d_in[3];   // [E]
    const float* eval = (const float*)d_in[4];   // [E]
    float* out = (float*)d_out;                  // [N, 256]

    const int M = in_sizes[0] / F_IN;            // 100000
    const int E = in_sizes[2];                   // 3200000

    // 1) zero output
    int n4 = out_size / 4;
    zero_kernel<<<(n4 + 255) / 256, 256>>>(out, n4);

    // 2) support = x @ W
    dim3 g1((M + 127) / 128, F_OUT / 128);
    gemm_kernel<<<g1, 256>>>(x, w, M);

    // 3) scatter-add
    dim3 g2((E + ECHUNK - 1) / ECHUNK, F_OUT / 128);
    spmm_kernel<<<g2, 128>>>(erow, ecol, eval, out, E);
}

// round 5
// speedup vs baseline: 1.6691x; 1.6691x over previous
#include <cuda_runtime.h>
#include <cuda_bf16.h>
#include <cstdint>

// Problem constants (fixed by the reference)
#define F_IN   512
#define F_OUT  256
#define MAX_NODES 100000
#define KC      64                 // K per chunk
#define NCHUNK  (F_IN / KC)        // 8
#define TILE_M  128

// ---------------------------------------------------------------------------
// Global scratch (allocation-free per harness rules)
// ---------------------------------------------------------------------------
__device__ float g_support[(size_t)MAX_NODES * F_OUT];                 // 102.4 MB
__device__ __nv_bfloat16 g_wt_hi[NCHUNK * F_OUT * KC];                 // 256 KB, [chunk][n][kk]
__device__ __nv_bfloat16 g_wt_lo[NCHUNK * F_OUT * KC];                 // 256 KB

// ---------------------------------------------------------------------------
// Helpers (baseline PTX only: ldmatrix sm_75+, mma.sync sm_80+ — no 'a' features)
// ---------------------------------------------------------------------------
__device__ __forceinline__ uint32_t smem_to_u32(const void* p) {
    uint32_t a;
    asm("{ .reg .u64 t; cvta.to.shared.u64 t, %1; cvt.u32.u64 %0, t; }" : "=r"(a) : "l"(p));
    return a;
}
#define STS128(r0, r1, r2, r3, addr) \
    asm volatile("st.shared.v4.b32 [%0], {%1, %2, %3, %4};" \
                 :: "r"(addr), "r"(r0), "r"(r1), "r"(r2), "r"(r3) : "memory")
#define LDSM_X4(r, addr) \
    asm volatile("ldmatrix.sync.aligned.m8n8.x4.shared.b16 {%0,%1,%2,%3}, [%4];" \
                 : "=r"((r)[0]), "=r"((r)[1]), "=r"((r)[2]), "=r"((r)[3]) : "r"(addr))
#define MMA_BF16(d, a, b0, b1) \
    asm volatile("mma.sync.aligned.m16n8k16.row.col.f32.bf16.bf16.f32 " \
                 "{%0,%1,%2,%3}, {%4,%5,%6,%7}, {%8,%9}, {%0,%1,%2,%3};" \
                 : "+f"((d)[0]), "+f"((d)[1]), "+f"((d)[2]), "+f"((d)[3]) \
                 : "r"((a)[0]), "r"((a)[1]), "r"((a)[2]), "r"((a)[3]), \
                   "r"(b0), "r"(b1))

// Padded SMEM row stride: 64 bf16 + 8 pad = 72 elem = 144 B (conflict-free ldmatrix)
#define ROWB    144
#define SM_AHI  0
#define SM_ALO  (SM_AHI + TILE_M * ROWB)    // 18432
#define SM_BHI  (SM_ALO + TILE_M * ROWB)    // 36864
#define SM_BLO  (SM_BHI + 128 * ROWB)       // 55296
#define SM_TOTAL (SM_BLO + 128 * ROWB)      // 73728 B

__device__ __forceinline__ void split_pack2(float a, float b, uint32_t& hi, uint32_t& lo) {
    __nv_bfloat16 ha = __float2bfloat16(a);
    __nv_bfloat16 hb = __float2bfloat16(b);
    __nv_bfloat162 hp; hp.x = ha; hp.y = hb;
    hi = *reinterpret_cast<uint32_t*>(&hp);
    __nv_bfloat16 la = __float2bfloat16(a - __bfloat162float(ha));
    __nv_bfloat16 lb = __float2bfloat16(b - __bfloat162float(hb));
    __nv_bfloat162 lp; lp.x = la; lp.y = lb;
    lo = *reinterpret_cast<uint32_t*>(&lp);
}

// ---------------------------------------------------------------------------
// W pre-pass: split W[512,256] fp32 -> hi/lo bf16, chunk-major [chunk][n][kk]
// (kk contiguous per n = exactly the col-major B layout mma.sync.row.col wants)
// ---------------------------------------------------------------------------
__global__ void convert_w_kernel(const float* __restrict__ W) {
    int n = blockIdx.x;           // 0..255
    int k = threadIdx.x;          // 0..511
    float v = W[(size_t)k * F_OUT + n];
    __nv_bfloat16 hi = __float2bfloat16(v);
    __nv_bfloat16 lo = __float2bfloat16(v - __bfloat162float(hi));
    int idx = (k >> 6) * (F_OUT * KC) + n * KC + (k & (KC - 1));
    g_wt_hi[idx] = hi;
    g_wt_lo[idx] = lo;
}

// ---------------------------------------------------------------------------
// Zero-init output
// ---------------------------------------------------------------------------
__global__ void zero_kernel(float* __restrict__ out, int n4) {
    int i = blockIdx.x * blockDim.x + threadIdx.x;
    float4 z = {0.f, 0.f, 0.f, 0.f};
    if (i < n4) reinterpret_cast<float4*>(out)[i] = z;
}

// ---------------------------------------------------------------------------
// Tensor-core GEMM via mma.sync (3-term bf16 split).
// CTA tile 128x128, 8 warps (4 m x 2 n), warp tile 32x64, K-chunk 64.
// ---------------------------------------------------------------------------
__global__ void __launch_bounds__(256, 2) gemm_mma_kernel(const float* __restrict__ A, int M) {
    extern __shared__ char smem[];
    const uint32_t sb = smem_to_u32(smem);
    const int tid = threadIdx.x;
    const int wid = tid >> 5;
    const int l   = tid & 31;
    const int warp_m = wid & 3;          // 0..3 -> 32 rows each
    const int warp_n = wid >> 2;         // 0..1 -> 64 cols each

    const int block_m = blockIdx.x * TILE_M;
    const int nblk    = blockIdx.y * 128;

    // A-tile fill mapping: 2 threads/row, 32 k-elements each
    const int ar = tid >> 1;
    const int ah = (tid & 1) * 32;
    const bool avalid = (block_m + ar) < M;
    const float* aptr = A + (size_t)(block_m + ar) * F_IN;

    // ldmatrix per-lane offsets (bytes)
    // A (x4): tiles [rows 0-7,k0][rows 8-15,k0][rows 0-7,k8][rows 8-15,k8]
    const uint32_t aoff = (uint32_t)((l & 15) * ROWB + ((l & 16) ? 16 : 0));
    // B (x4): tiles [n 0-7,k0][n 0-7,k8][n 8-15,k0][n 8-15,k8]
    const uint32_t boff = (uint32_t)((((l & 7) + ((l & 16) ? 8 : 0)) * ROWB) + ((l & 8) ? 16 : 0));

    const uint32_t abase_hi = sb + SM_AHI + (uint32_t)(warp_m * 32) * ROWB + aoff;
    const uint32_t abase_lo = sb + SM_ALO + (uint32_t)(warp_m * 32) * ROWB + aoff;
    const uint32_t bbase_hi = sb + SM_BHI + (uint32_t)(warp_n * 64) * ROWB + boff;
    const uint32_t bbase_lo = sb + SM_BLO + (uint32_t)(warp_n * 64) * ROWB + boff;

    float acc[2][8][4];
    #pragma unroll
    for (int i = 0; i < 2; i++)
        #pragma unroll
        for (int j = 0; j < 8; j++)
            #pragma unroll
            for (int q = 0; q < 4; q++)
                acc[i][j][q] = 0.f;

    const uint4* wh4 = reinterpret_cast<const uint4*>(g_wt_hi);
    const uint4* wl4 = reinterpret_cast<const uint4*>(g_wt_lo);

    for (int chunk = 0; chunk < NCHUNK; ++chunk) {
        __syncthreads();   // all warps done with previous chunk's SMEM

        // ---- A tile: fp32 -> (hi, lo) bf16, padded rows ----
        const int k0 = chunk * KC;
        #pragma unroll
        for (int j = 0; j < 4; ++j) {
            const int c = ah + j * 8;
            float4 v0 = {0.f, 0.f, 0.f, 0.f}, v1 = v0;
            if (avalid) {
                v0 = *reinterpret_cast<const float4*>(aptr + k0 + c);
                v1 = *reinterpret_cast<const float4*>(aptr + k0 + c + 4);
            }
            uint32_t h0, h1, h2, h3, l0, l1, l2, l3;
            split_pack2(v0.x, v0.y, h0, l0);
            split_pack2(v0.z, v0.w, h1, l1);
            split_pack2(v1.x, v1.y, h2, l2);
            split_pack2(v1.z, v1.w, h3, l3);
            const uint32_t off = (uint32_t)(ar * ROWB + c * 2);
            STS128(h0, h1, h2, h3, sb + SM_AHI + off);
            STS128(l0, l1, l2, l3, sb + SM_ALO + off);
        }

        // ---- B tile: [128 n][64 kk] hi/lo, 16B copies into padded rows ----
        {
            const uint4* bh = wh4 + chunk * 2048 + nblk * 8;   // 8 uint4 per n-row
            const uint4* bl = wl4 + chunk * 2048 + nblk * 8;
            #pragma unroll
            for (int t = tid; t < 1024; t += 256) {
                const int n = t >> 3, u = t & 7;
                uint4 vh = bh[n * 8 + u];
                uint4 vl = bl[n * 8 + u];
                const uint32_t off = (uint32_t)(n * ROWB + u * 16);
                STS128(vh.x, vh.y, vh.z, vh.w, sb + SM_BHI + off);
                STS128(vl.x, vl.y, vl.z, vl.w, sb + SM_BLO + off);
            }
        }
        __syncthreads();

        // ---- MMA over 4 K-steps of 16 ----
        #pragma unroll
        for (int ks = 0; ks < 4; ++ks) {
            uint32_t ahf[2][4], alf[2][4];
            #pragma unroll
            for (int i = 0; i < 2; ++i) {
                LDSM_X4(ahf[i], abase_hi + (uint32_t)(i * 16 * ROWB) + ks * 32);
                LDSM_X4(alf[i], abase_lo + (uint32_t)(i * 16 * ROWB) + ks * 32);
            }
            #pragma unroll
            for (int jp = 0; jp < 4; ++jp) {
                uint32_t bhf[4], blf[4];
                LDSM_X4(bhf, bbase_hi + (uint32_t)(jp * 16 * ROWB) + ks * 32);
                LDSM_X4(blf, bbase_lo + (uint32_t)(jp * 16 * ROWB) + ks * 32);
                #pragma unroll
                for (int i = 0; i < 2; ++i) {
                    #pragma unroll
                    for (int jj = 0; jj < 2; ++jj) {
                        const int j = jp * 2 + jj;
                        MMA_BF16(acc[i][j], ahf[i], bhf[jj * 2], bhf[jj * 2 + 1]);
                        MMA_BF16(acc[i][j], ahf[i], blf[jj * 2], blf[jj * 2 + 1]);
                        MMA_BF16(acc[i][j], alf[i], bhf[jj * 2], bhf[jj * 2 + 1]);
                    }
                }
            }
        }
    }

    // ---- epilogue: c0,c1 at (row, col..col+1); c2,c3 at (row+8, ...) ----
    const int row0 = block_m + warp_m * 32 + (l >> 2);
    const int col0 = nblk + warp_n * 64 + (l & 3) * 2;
    #pragma unroll
    for (int i = 0; i < 2; ++i) {
        const int row = row0 + i * 16;
        #pragma unroll
        for (int j = 0; j < 8; ++j) {
            const int col = col0 + j * 8;
            if (row < M) {
                float2 v01 = {acc[i][j][0], acc[i][j][1]};
                *reinterpret_cast<float2*>(g_support + (size_t)row * F_OUT + col) = v01;
            }
            if (row + 8 < M) {
                float2 v23 = {acc[i][j][2], acc[i][j][3]};
                *reinterpret_cast<float2*>(g_support + (size_t)(row + 8) * F_OUT + col) = v23;
            }
        }
    }
}

// ---------------------------------------------------------------------------
// SpMM: out[row] += val * support[col], edges row-sorted (unchanged)
// ---------------------------------------------------------------------------
#define ECHUNK 256
#define SPMM_UNROLL 8

__global__ void __launch_bounds__(128) spmm_kernel(
    const int*   __restrict__ erow,
    const int*   __restrict__ ecol,
    const float* __restrict__ eval,
    float*       __restrict__ out,
    int E)
{
    __shared__ int   srow[ECHUNK];
    __shared__ int   scol[ECHUNK];
    __shared__ float sval[ECHUNK];

    const int f  = blockIdx.y * 128 + threadIdx.x;
    const int e0 = blockIdx.x * ECHUNK;
    const int n  = min(ECHUNK, E - e0);

    for (int i = threadIdx.x; i < n; i += 128) {
        srow[i] = erow[e0 + i];
        scol[i] = ecol[e0 + i];
        sval[i] = eval[e0 + i];
    }
    for (int i = n + threadIdx.x; i < ECHUNK; i += 128) {
        scol[i] = 0;
        sval[i] = 0.f;
    }
    __syncthreads();
    if (n < ECHUNK) {
        int last = srow[n - 1];
        for (int i = n + threadIdx.x; i < ECHUNK; i += 128) srow[i] = last;
        __syncthreads();
    }

    float acc = 0.f;
    int   cur = srow[0];

    #pragma unroll 1
    for (int i = 0; i < ECHUNK; i += SPMM_UNROLL) {
        float g[SPMM_UNROLL];
        #pragma unroll
        for (int j = 0; j < SPMM_UNROLL; j++) {
            g[j] = __ldg(&g_support[(size_t)scol[i + j] * F_OUT + f]);
        }
        #pragma unroll
        for (int j = 0; j < SPMM_UNROLL; j++) {
            int r = srow[i + j];
            if (r != cur) {
                atomicAdd(&out[(size_t)cur * F_OUT + f], acc);
                acc = 0.f;
                cur = r;
            }
            acc = fmaf(sval[i + j], g[j], acc);
        }
    }
    atomicAdd(&out[(size_t)cur * F_OUT + f], acc);
}

// ---------------------------------------------------------------------------
extern "C" void kernel_launch(void* const* d_in, const int* in_sizes, int n_in,
                              void* d_out, int out_size) {
    const float* x    = (const float*)d_in[0];   // [N, 512]
    const float* w    = (const float*)d_in[1];   // [512, 256]
    const int*   erow = (const int*)  d_in[2];   // [E]
    const int*   ecol = (const int*)  d_in[3];   // [E]
    const float* eval = (const float*)d_in[4];   // [E]
    float* out = (float*)d_out;                  // [N, 256]

    const int M = in_sizes[0] / F_IN;            // 100000
    const int E = in_sizes[2];                   // 3200000

    // 0) split + reorder W into bf16 hi/lo (tiny)
    convert_w_kernel<<<F_OUT, F_IN>>>(w);

    // 1) zero output
    int n4 = out_size / 4;
    zero_kernel<<<(n4 + 255) / 256, 256>>>(out, n4);

    // 2) support = x @ W on tensor cores (mma.sync, 3-term bf16 split)
    cudaFuncSetAttribute(gemm_mma_kernel, cudaFuncAttributeMaxDynamicSharedMemorySize, SM_TOTAL);
    dim3 g1((M + TILE_M - 1) / TILE_M, F_OUT / 128);
    gemm_mma_kernel<<<g1, 256, SM_TOTAL>>>(x, M);

    // 3) scatter-add
    dim3 g2((E + ECHUNK - 1) / ECHUNK, F_OUT / 128);
    spmm_kernel<<<g2, 128>>>(erow, ecol, eval, out, E);
}

// round 7
// speedup vs baseline: 1.6709x; 1.0010x over previous
#include <cuda_runtime.h>
#include <cuda_bf16.h>
#include <cstdint>

// Problem constants (fixed by the reference)
#define F_IN   512
#define F_OUT  256
#define MAX_NODES 100000
#define KC      64                 // K per chunk
#define NCHUNK  (F_IN / KC)        // 8
#define TILE_M  128

// ---------------------------------------------------------------------------
// Global scratch (allocation-free per harness rules)
// ---------------------------------------------------------------------------
__device__ float g_support[(size_t)MAX_NODES * F_OUT];                 // 102.4 MB
__device__ __nv_bfloat16 g_wt_hi[NCHUNK * F_OUT * KC];                 // 256 KB, [chunk][n][kk]
__device__ __nv_bfloat16 g_wt_lo[NCHUNK * F_OUT * KC];                 // 256 KB

// ---------------------------------------------------------------------------
// Helpers (baseline PTX only: ldmatrix sm_75+, mma.sync sm_80+ — no 'a' features)
// ---------------------------------------------------------------------------
__device__ __forceinline__ uint32_t smem_to_u32(const void* p) {
    uint32_t a;
    asm("{ .reg .u64 t; cvta.to.shared.u64 t, %1; cvt.u32.u64 %0, t; }" : "=r"(a) : "l"(p));
    return a;
}
#define STS128(r0, r1, r2, r3, addr) \
    asm volatile("st.shared.v4.b32 [%0], {%1, %2, %3, %4};" \
                 :: "r"(addr), "r"(r0), "r"(r1), "r"(r2), "r"(r3) : "memory")
#define LDSM_X4(r, addr) \
    asm volatile("ldmatrix.sync.aligned.m8n8.x4.shared.b16 {%0,%1,%2,%3}, [%4];" \
                 : "=r"((r)[0]), "=r"((r)[1]), "=r"((r)[2]), "=r"((r)[3]) : "r"(addr))
#define MMA_BF16(d, a, b0, b1) \
    asm volatile("mma.sync.aligned.m16n8k16.row.col.f32.bf16.bf16.f32 " \
                 "{%0,%1,%2,%3}, {%4,%5,%6,%7}, {%8,%9}, {%0,%1,%2,%3};" \
                 : "+f"((d)[0]), "+f"((d)[1]), "+f"((d)[2]), "+f"((d)[3]) \
                 : "r"((a)[0]), "r"((a)[1]), "r"((a)[2]), "r"((a)[3]), \
                   "r"(b0), "r"(b1))

// Padded SMEM row stride: 64 bf16 + 8 pad = 72 elem = 144 B (conflict-free ldmatrix)
#define ROWB    144
#define SM_AHI  0
#define SM_ALO  (SM_AHI + TILE_M * ROWB)    // 18432
#define SM_BHI  (SM_ALO + TILE_M * ROWB)    // 36864
#define SM_BLO  (SM_BHI + 128 * ROWB)       // 55296
#define SM_TOTAL (SM_BLO + 128 * ROWB)      // 73728 B

__device__ __forceinline__ void split_pack2(float a, float b, uint32_t& hi, uint32_t& lo) {
    __nv_bfloat16 ha = __float2bfloat16(a);
    __nv_bfloat16 hb = __float2bfloat16(b);
    __nv_bfloat162 hp; hp.x = ha; hp.y = hb;
    hi = *reinterpret_cast<uint32_t*>(&hp);
    __nv_bfloat16 la = __float2bfloat16(a - __bfloat162float(ha));
    __nv_bfloat16 lb = __float2bfloat16(b - __bfloat162float(hb));
    __nv_bfloat162 lp; lp.x = la; lp.y = lb;
    lo = *reinterpret_cast<uint32_t*>(&lp);
}

// ---------------------------------------------------------------------------
// W pre-pass: split W[512,256] fp32 -> hi/lo bf16, chunk-major [chunk][n][kk]
// (kk contiguous per n = exactly the col-major B layout mma.sync.row.col wants)
// ---------------------------------------------------------------------------
__global__ void convert_w_kernel(const float* __restrict__ W) {
    int n = blockIdx.x;           // 0..255
    int k = threadIdx.x;          // 0..511
    float v = W[(size_t)k * F_OUT + n];
    __nv_bfloat16 hi = __float2bfloat16(v);
    __nv_bfloat16 lo = __float2bfloat16(v - __bfloat162float(hi));
    int idx = (k >> 6) * (F_OUT * KC) + n * KC + (k & (KC - 1));
    g_wt_hi[idx] = hi;
    g_wt_lo[idx] = lo;
}

// ---------------------------------------------------------------------------
// Zero-init output
// ---------------------------------------------------------------------------
__global__ void zero_kernel(float* __restrict__ out, int n4) {
    int i = blockIdx.x * blockDim.x + threadIdx.x;
    float4 z = {0.f, 0.f, 0.f, 0.f};
    if (i < n4) reinterpret_cast<float4*>(out)[i] = z;
}

// ---------------------------------------------------------------------------
// Tensor-core GEMM via mma.sync (3-term bf16 split).
// CTA tile 128x128, 8 warps (4 m x 2 n), warp tile 32x64, K-chunk 64.
// ---------------------------------------------------------------------------
__global__ void __launch_bounds__(256, 2) gemm_mma_kernel(const float* __restrict__ A, int M) {
    extern __shared__ char smem[];
    const uint32_t sb = smem_to_u32(smem);
    const int tid = threadIdx.x;
    const int wid = tid >> 5;
    const int l   = tid & 31;
    const int warp_m = wid & 3;          // 0..3 -> 32 rows each
    const int warp_n = wid >> 2;         // 0..1 -> 64 cols each

    const int block_m = blockIdx.x * TILE_M;
    const int nblk    = blockIdx.y * 128;

    // A-tile fill mapping: 2 threads/row, 32 k-elements each
    const int ar = tid >> 1;
    const int ah = (tid & 1) * 32;
    const bool avalid = (block_m + ar) < M;
    const float* aptr = A + (size_t)(block_m + ar) * F_IN;

    // ldmatrix per-lane offsets (bytes)
    // A (x4): tiles [rows 0-7,k0][rows 8-15,k0][rows 0-7,k8][rows 8-15,k8]
    const uint32_t aoff = (uint32_t)((l & 15) * ROWB + ((l & 16) ? 16 : 0));
    // B (x4): tiles [n 0-7,k0][n 0-7,k8][n 8-15,k0][n 8-15,k8]
    const uint32_t boff = (uint32_t)((((l & 7) + ((l & 16) ? 8 : 0)) * ROWB) + ((l & 8) ? 16 : 0));

    const uint32_t abase_hi = sb + SM_AHI + (uint32_t)(warp_m * 32) * ROWB + aoff;
    const uint32_t abase_lo = sb + SM_ALO + (uint32_t)(warp_m * 32) * ROWB + aoff;
    const uint32_t bbase_hi = sb + SM_BHI + (uint32_t)(warp_n * 64) * ROWB + boff;
    const uint32_t bbase_lo = sb + SM_BLO + (uint32_t)(warp_n * 64) * ROWB + boff;

    float acc[2][8][4];
    #pragma unroll
    for (int i = 0; i < 2; i++)
        #pragma unroll
        for (int j = 0; j < 8; j++)
            #pragma unroll
            for (int q = 0; q < 4; q++)
                acc[i][j][q] = 0.f;

    const uint4* wh4 = reinterpret_cast<const uint4*>(g_wt_hi);
    const uint4* wl4 = reinterpret_cast<const uint4*>(g_wt_lo);

    for (int chunk = 0; chunk < NCHUNK; ++chunk) {
        __syncthreads();   // all warps done with previous chunk's SMEM

        // ---- A tile: fp32 -> (hi, lo) bf16, padded rows ----
        const int k0 = chunk * KC;
        #pragma unroll
        for (int j = 0; j < 4; ++j) {
            const int c = ah + j * 8;
            float4 v0 = {0.f, 0.f, 0.f, 0.f}, v1 = v0;
            if (avalid) {
                v0 = *reinterpret_cast<const float4*>(aptr + k0 + c);
                v1 = *reinterpret_cast<const float4*>(aptr + k0 + c + 4);
            }
            uint32_t h0, h1, h2, h3, l0, l1, l2, l3;
            split_pack2(v0.x, v0.y, h0, l0);
            split_pack2(v0.z, v0.w, h1, l1);
            split_pack2(v1.x, v1.y, h2, l2);
            split_pack2(v1.z, v1.w, h3, l3);
            const uint32_t off = (uint32_t)(ar * ROWB + c * 2);
            STS128(h0, h1, h2, h3, sb + SM_AHI + off);
            STS128(l0, l1, l2, l3, sb + SM_ALO + off);
        }

        // ---- B tile: [128 n][64 kk] hi/lo, 16B copies into padded rows ----
        {
            const uint4* bh = wh4 + chunk * 2048 + nblk * 8;   // 8 uint4 per n-row
            const uint4* bl = wl4 + chunk * 2048 + nblk * 8;
            #pragma unroll
            for (int t = tid; t < 1024; t += 256) {
                const int n = t >> 3, u = t & 7;
                uint4 vh = bh[n * 8 + u];
                uint4 vl = bl[n * 8 + u];
                const uint32_t off = (uint32_t)(n * ROWB + u * 16);
                STS128(vh.x, vh.y, vh.z, vh.w, sb + SM_BHI + off);
                STS128(vl.x, vl.y, vl.z, vl.w, sb + SM_BLO + off);
            }
        }
        __syncthreads();

        // ---- MMA over 4 K-steps of 16 ----
        #pragma unroll
        for (int ks = 0; ks < 4; ++ks) {
            uint32_t ahf[2][4], alf[2][4];
            #pragma unroll
            for (int i = 0; i < 2; ++i) {
                LDSM_X4(ahf[i], abase_hi + (uint32_t)(i * 16 * ROWB) + ks * 32);
                LDSM_X4(alf[i], abase_lo + (uint32_t)(i * 16 * ROWB) + ks * 32);
            }
            #pragma unroll
            for (int jp = 0; jp < 4; ++jp) {
                uint32_t bhf[4], blf[4];
                LDSM_X4(bhf, bbase_hi + (uint32_t)(jp * 16 * ROWB) + ks * 32);
                LDSM_X4(blf, bbase_lo + (uint32_t)(jp * 16 * ROWB) + ks * 32);
                #pragma unroll
                for (int i = 0; i < 2; ++i) {
                    #pragma unroll
                    for (int jj = 0; jj < 2; ++jj) {
                        const int j = jp * 2 + jj;
                        MMA_BF16(acc[i][j], ahf[i], bhf[jj * 2], bhf[jj * 2 + 1]);
                        MMA_BF16(acc[i][j], ahf[i], blf[jj * 2], blf[jj * 2 + 1]);
                        MMA_BF16(acc[i][j], alf[i], bhf[jj * 2], bhf[jj * 2 + 1]);
                    }
                }
            }
        }
    }

    // ---- epilogue: c0,c1 at (row, col..col+1); c2,c3 at (row+8, ...) ----
    const int row0 = block_m + warp_m * 32 + (l >> 2);
    const int col0 = nblk + warp_n * 64 + (l & 3) * 2;
    #pragma unroll
    for (int i = 0; i < 2; ++i) {
        const int row = row0 + i * 16;
        #pragma unroll
        for (int j = 0; j < 8; ++j) {
            const int col = col0 + j * 8;
            if (row < M) {
                float2 v01 = {acc[i][j][0], acc[i][j][1]};
                *reinterpret_cast<float2*>(g_support + (size_t)row * F_OUT + col) = v01;
            }
            if (row + 8 < M) {
                float2 v23 = {acc[i][j][2], acc[i][j][3]};
                *reinterpret_cast<float2*>(g_support + (size_t)(row + 8) * F_OUT + col) = v23;
            }
        }
    }
}

// ---------------------------------------------------------------------------
// SpMM: out[row] += val * support[col], edges row-sorted (unchanged)
// ---------------------------------------------------------------------------
#define ECHUNK 256
#define SPMM_UNROLL 8

__global__ void __launch_bounds__(128) spmm_kernel(
    const int*   __restrict__ erow,
    const int*   __restrict__ ecol,
    const float* __restrict__ eval,
    float*       __restrict__ out,
    int E)
{
    __shared__ int   srow[ECHUNK];
    __shared__ int   scol[ECHUNK];
    __shared__ float sval[ECHUNK];

    const int f  = blockIdx.y * 128 + threadIdx.x;
    const int e0 = blockIdx.x * ECHUNK;
    const int n  = min(ECHUNK, E - e0);

    for (int i = threadIdx.x; i < n; i += 128) {
        srow[i] = erow[e0 + i];
        scol[i] = ecol[e0 + i];
        sval[i] = eval[e0 + i];
    }
    for (int i = n + threadIdx.x; i < ECHUNK; i += 128) {
        scol[i] = 0;
        sval[i] = 0.f;
    }
    __syncthreads();
    if (n < ECHUNK) {
        int last = srow[n - 1];
        for (int i = n + threadIdx.x; i < ECHUNK; i += 128) srow[i] = last;
        __syncthreads();
    }

    float acc = 0.f;
    int   cur = srow[0];

    #pragma unroll 1
    for (int i = 0; i < ECHUNK; i += SPMM_UNROLL) {
        float g[SPMM_UNROLL];
        #pragma unroll
        for (int j = 0; j < SPMM_UNROLL; j++) {
            g[j] = __ldg(&g_support[(size_t)scol[i + j] * F_OUT + f]);
        }
        #pragma unroll
        for (int j = 0; j < SPMM_UNROLL; j++) {
            int r = srow[i + j];
            if (r != cur) {
                atomicAdd(&out[(size_t)cur * F_OUT + f], acc);
                acc = 0.f;
                cur = r;
            }
            acc = fmaf(sval[i + j], g[j], acc);
        }
    }
    atomicAdd(&out[(size_t)cur * F_OUT + f], acc);
}

// ---------------------------------------------------------------------------
extern "C" void kernel_launch(void* const* d_in, const int* in_sizes, int n_in,
                              void* d_out, int out_size) {
    const float* x    = (const float*)d_in[0];   // [N, 512]
    const float* w    = (const float*)d_in[1];   // [512, 256]
    const int*   erow = (const int*)  d_in[2];   // [E]
    const int*   ecol = (const int*)  d_in[3];   // [E]
    const float* eval = (const float*)d_in[4];   // [E]
    float* out = (float*)d_out;                  // [N, 256]

    const int M = in_sizes[0] / F_IN;            // 100000
    const int E = in_sizes[2];                   // 3200000

    // 0) split + reorder W into bf16 hi/lo (tiny)
    convert_w_kernel<<<F_OUT, F_IN>>>(w);

    // 1) zero output
    int n4 = out_size / 4;
    zero_kernel<<<(n4 + 255) / 256, 256>>>(out, n4);

    // 2) support = x @ W on tensor cores (mma.sync, 3-term bf16 split)
    cudaFuncSetAttribute(gemm_mma_kernel, cudaFuncAttributeMaxDynamicSharedMemorySize, SM_TOTAL);
    dim3 g1((M + TILE_M - 1) / TILE_M, F_OUT / 128);
    gemm_mma_kernel<<<g1, 256, SM_TOTAL>>>(x, M);

    // 3) scatter-add
    dim3 g2((E + ECHUNK - 1) / ECHUNK, F_OUT / 128);
    spmm_kernel<<<g2, 128>>>(erow, ecol, eval, out, E);
}